// round 5
// baseline (speedup 1.0000x reference)
#include <cuda_runtime.h>
#include <math.h>
#include <stdint.h>

#define Bsz 2
#define Tsz 2048
#define Csz 1024
#define NH 16
#define NKV 4
#define HD 64
#define Mrows (Bsz*Tsz)      // 4096
#define KVC (NKV*HD)         // 256
#define QB 64                // q rows per attention CTA

// Scratch (device globals: no allocation allowed)
__device__ float g_q [Mrows*Csz];
__device__ float g_k [Mrows*KVC];
__device__ float g_v [Mrows*KVC];
__device__ float g_ao[Mrows*Csz];

__device__ __forceinline__ float tf32r(float x) {
    uint32_t u; asm("cvt.rna.tf32.f32 %0, %1;" : "=r"(u) : "f"(x));
    return __uint_as_float(u);
}

__device__ __forceinline__ void mma_tf32(float c[4], const uint32_t a[4], const uint32_t b[2]) {
    asm volatile(
        "mma.sync.aligned.m16n8k8.row.col.f32.tf32.tf32.f32 "
        "{%0,%1,%2,%3}, {%4,%5,%6,%7}, {%8,%9}, {%0,%1,%2,%3};\n"
        : "+f"(c[0]), "+f"(c[1]), "+f"(c[2]), "+f"(c[3])
        : "r"(a[0]), "r"(a[1]), "r"(a[2]), "r"(a[3]), "r"(b[0]), "r"(b[1]));
}

// ---------------------------------------------------------------------------
// tf32 tensor-core GEMM (unchanged from R4 — proven).
// C[M,N] = A[M,K] @ W[K,N] + bias ; optional fused interleaved RoPE.
// Block 128x64, BK=16, 8 warps 4(m)x2(n), warp tile 32x32.
// ---------------------------------------------------------------------------
template<bool DO_ROPE>
__global__ __launch_bounds__(256)
void gemm_tf32(const float* __restrict__ A, const float* __restrict__ W,
               const float* __restrict__ bias, float* __restrict__ C,
               int M, int K, int N)
{
    __shared__ float As[16][136];   // k-major: As[k][m]
    __shared__ float Bs[16][72];    // Bs[k][n]

    int tid = threadIdx.x;
    int lane = tid & 31, w = tid >> 5;
    int g = lane >> 2, tg = lane & 3;
    int wm = (w & 3) * 32, wn = (w >> 2) * 32;
    int m0 = blockIdx.y * 128, n0 = blockIdx.x * 64;

    int ar0 = tid >> 2, ar1 = (tid + 256) >> 2, ac4 = tid & 3;
    int br  = tid >> 4, bc4 = tid & 15;

    float acc[2][4][4] = {};
    float4 areg0, areg1, breg;

    auto ldt = [&](int k0) {
        areg0 = *(const float4*)(A + (size_t)(m0 + ar0) * K + k0 + ac4 * 4);
        areg1 = *(const float4*)(A + (size_t)(m0 + ar1) * K + k0 + ac4 * 4);
        breg  = *(const float4*)(W + (size_t)(k0 + br) * N + n0 + bc4 * 4);
    };

    int niter = K / 16;
    ldt(0);

    for (int i = 0; i < niter; i++) {
        __syncthreads();
        As[ac4*4+0][ar0] = tf32r(areg0.x);
        As[ac4*4+1][ar0] = tf32r(areg0.y);
        As[ac4*4+2][ar0] = tf32r(areg0.z);
        As[ac4*4+3][ar0] = tf32r(areg0.w);
        As[ac4*4+0][ar1] = tf32r(areg1.x);
        As[ac4*4+1][ar1] = tf32r(areg1.y);
        As[ac4*4+2][ar1] = tf32r(areg1.z);
        As[ac4*4+3][ar1] = tf32r(areg1.w);
        {
            float4 u = make_float4(tf32r(breg.x), tf32r(breg.y),
                                   tf32r(breg.z), tf32r(breg.w));
            *(float4*)&Bs[br][bc4*4] = u;
        }
        __syncthreads();

        if (i + 1 < niter) ldt((i + 1) * 16);

#pragma unroll
        for (int ks = 0; ks < 2; ks++) {
            uint32_t af[2][4], bf[4][2];
#pragma unroll
            for (int mt = 0; mt < 2; mt++) {
                int mr = wm + mt * 16;
                af[mt][0] = __float_as_uint(As[ks*8+tg  ][mr+g  ]);
                af[mt][1] = __float_as_uint(As[ks*8+tg  ][mr+g+8]);
                af[mt][2] = __float_as_uint(As[ks*8+tg+4][mr+g  ]);
                af[mt][3] = __float_as_uint(As[ks*8+tg+4][mr+g+8]);
            }
#pragma unroll
            for (int nt = 0; nt < 4; nt++) {
                bf[nt][0] = __float_as_uint(Bs[ks*8+tg  ][wn+nt*8+g]);
                bf[nt][1] = __float_as_uint(Bs[ks*8+tg+4][wn+nt*8+g]);
            }
#pragma unroll
            for (int mt = 0; mt < 2; mt++)
#pragma unroll
                for (int nt = 0; nt < 4; nt++)
                    mma_tf32(acc[mt][nt], af[mt], bf[nt]);
        }
    }

#pragma unroll
    for (int mt = 0; mt < 2; mt++) {
        int r0 = m0 + wm + mt * 16 + g;
#pragma unroll
        for (int nt = 0; nt < 4; nt++) {
            int c = n0 + wn + nt * 8 + tg * 2;
            float2 bb = *(const float2*)(bias + c);
            float2 v0 = make_float2(acc[mt][nt][0] + bb.x, acc[mt][nt][1] + bb.y);
            float2 v1 = make_float2(acc[mt][nt][2] + bb.x, acc[mt][nt][3] + bb.y);
            if (DO_ROPE) {
                int pair = (c & (HD - 1)) >> 1;
                float inv = powf(10000.0f, -(float)(2 * pair) / (float)HD);
                float sn0, cs0, sn1, cs1;
                sincosf((float)(r0 & (Tsz - 1)) * inv, &sn0, &cs0);
                sincosf((float)((r0 + 8) & (Tsz - 1)) * inv, &sn1, &cs1);
                float e0 = v0.x, o0 = v0.y;
                v0.x = e0 * cs0 - o0 * sn0;  v0.y = e0 * sn0 + o0 * cs0;
                float e1 = v1.x, o1 = v1.y;
                v1.x = e1 * cs1 - o1 * sn1;  v1.y = e1 * sn1 + o1 * cs1;
            }
            *(float2*)(C + (size_t)r0 * N + c)       = v0;
            *(float2*)(C + (size_t)(r0 + 8) * N + c) = v1;
        }
    }
}

// ---------------------------------------------------------------------------
// Flash attention, tf32 tensor cores. RESTRUCTURED for occupancy:
// CTA: 64 q-rows x 1 head, 256 threads, 2 CTAs/SM.
// 8 warps = 4(m, 16 rows each) x 2(n, 32 cols each). K/V register prefetch.
// ---------------------------------------------------------------------------
__global__ __launch_bounds__(256, 2)
void attn_tf32(const float* __restrict__ q, const float* __restrict__ k,
               const float* __restrict__ v, float* __restrict__ o)
{
    extern __shared__ float sm[];
    float (*Qs)[68] = (float(*)[68])sm;                          // [64][68]
    float (*Ks)[72] = (float(*)[72])(sm + QB*68);                // [64][72]  d-major
    float (*Vs)[72] = (float(*)[72])(sm + QB*68 + 64*72);        // [64][72]  key-major
    float (*Ps)[68] = (float(*)[68])(sm + QB*68 + 2*64*72);      // [64][68]
    float2* red     = (float2*)(sm + 2*QB*68 + 2*64*72);         // [64][2]

    int b  = blockIdx.z;
    int h  = blockIdx.y;
    int qb = gridDim.x - 1 - blockIdx.x;   // heavy blocks first
    int q0 = qb * QB;
    int kvh = h >> 2;

    int tid = threadIdx.x;
    int lane = tid & 31, w = tid >> 5;
    int g = lane >> 2, tg = lane & 3;
    int wm = (w >> 1) * 16;    // warp row origin (0,16,32,48)
    int wn = w & 1;            // warp col half

    // load Q tile (pre-scaled by 1/8, tf32-rounded)
    {
        const float* qbase = q + (size_t)(b * Tsz + q0) * Csz + h * HD;
#pragma unroll
        for (int p = 0; p < 4; p++) {
            int i4 = tid + p * 256;
            int r = i4 >> 4, c4 = i4 & 15;
            float4 t = *(const float4*)(qbase + (size_t)r * Csz + c4 * 4);
            float4 u = make_float4(tf32r(t.x * 0.125f), tf32r(t.y * 0.125f),
                                   tf32r(t.z * 0.125f), tf32r(t.w * 0.125f));
            *(float4*)&Qs[r][c4*4] = u;
        }
    }

    float mrun[2], lrun[2];
    float oacc[4][4] = {};
#pragma unroll
    for (int ri = 0; ri < 2; ri++) { mrun[ri] = -1e30f; lrun[ri] = 0.f; }

    float4 kreg[4], vreg[4];
    auto ldkv = [&](int kb) {
        const float* kp = k + (size_t)(b * Tsz + kb * 64) * KVC + kvh * HD;
        const float* vp = v + (size_t)(b * Tsz + kb * 64) * KVC + kvh * HD;
#pragma unroll
        for (int p = 0; p < 4; p++) {
            int idx = tid + p * 256;
            int key = idx & 63, c4 = idx >> 6;
            kreg[p] = *(const float4*)(kp + (size_t)key * KVC + c4 * 4);
            vreg[p] = *(const float4*)(vp + (size_t)key * KVC + c4 * 4);
        }
    };

    ldkv(0);

    for (int kb = 0; kb <= qb; kb++) {
        __syncthreads();   // Qs ready (first iter) / Ks,Vs,Ps consumed (later)
        // stage prefetched K (d-major) / V (key-major), tf32-rounded
#pragma unroll
        for (int p = 0; p < 4; p++) {
            int idx = tid + p * 256;
            int key = idx & 63, c4 = idx >> 6;
            Ks[c4*4+0][key] = tf32r(kreg[p].x);
            Ks[c4*4+1][key] = tf32r(kreg[p].y);
            Ks[c4*4+2][key] = tf32r(kreg[p].z);
            Ks[c4*4+3][key] = tf32r(kreg[p].w);
            float4 uu = make_float4(tf32r(vreg[p].x), tf32r(vreg[p].y),
                                    tf32r(vreg[p].z), tf32r(vreg[p].w));
            *(float4*)&Vs[key][c4*4] = uu;
        }
        __syncthreads();

        if (kb < qb) ldkv(kb + 1);   // overlap next tile's LDGs

        // S = Q K^T  (warp tile 16x32)
        float s[4][4] = {};
#pragma unroll
        for (int ks = 0; ks < 8; ks++) {
            uint32_t af[4], bf[4][2];
            af[0] = __float_as_uint(Qs[wm+g  ][ks*8+tg  ]);
            af[1] = __float_as_uint(Qs[wm+g+8][ks*8+tg  ]);
            af[2] = __float_as_uint(Qs[wm+g  ][ks*8+tg+4]);
            af[3] = __float_as_uint(Qs[wm+g+8][ks*8+tg+4]);
#pragma unroll
            for (int nt = 0; nt < 4; nt++) {
                bf[nt][0] = __float_as_uint(Ks[ks*8+tg  ][wn*32+nt*8+g]);
                bf[nt][1] = __float_as_uint(Ks[ks*8+tg+4][wn*32+nt*8+g]);
            }
#pragma unroll
            for (int nt = 0; nt < 4; nt++)
                mma_tf32(s[nt], af, bf[nt]);
        }

        // causal mask (only on the diagonal tile)
        if (kb == qb) {
            int row0 = q0 + wm + g;
#pragma unroll
            for (int nt = 0; nt < 4; nt++) {
                int col = kb * 64 + wn * 32 + nt * 8 + 2 * tg;
                if (col     > row0    ) s[nt][0] = -1e30f;
                if (col + 1 > row0    ) s[nt][1] = -1e30f;
                if (col     > row0 + 8) s[nt][2] = -1e30f;
                if (col + 1 > row0 + 8) s[nt][3] = -1e30f;
            }
        }

        // per-warp-half row max + exp + sum
        float mh[2], sh[2];
#pragma unroll
        for (int ri = 0; ri < 2; ri++) {
            float mx = -1e30f;
#pragma unroll
            for (int nt = 0; nt < 4; nt++) {
                mx = fmaxf(mx, s[nt][2*ri]);
                mx = fmaxf(mx, s[nt][2*ri+1]);
            }
            mx = fmaxf(mx, __shfl_xor_sync(0xffffffffu, mx, 1));
            mx = fmaxf(mx, __shfl_xor_sync(0xffffffffu, mx, 2));
            float sum = 0.f;
#pragma unroll
            for (int nt = 0; nt < 4; nt++) {
                float p0 = __expf(s[nt][2*ri]   - mx);
                float p1 = __expf(s[nt][2*ri+1] - mx);
                s[nt][2*ri] = p0; s[nt][2*ri+1] = p1;
                sum += p0 + p1;
            }
            sum += __shfl_xor_sync(0xffffffffu, sum, 1);
            sum += __shfl_xor_sync(0xffffffffu, sum, 2);
            mh[ri] = mx; sh[ri] = sum;
        }

        if (tg == 0) {
#pragma unroll
            for (int ri = 0; ri < 2; ri++)
                red[(wm + ri*8 + g) * 2 + wn] = make_float2(mh[ri], sh[ri]);
        }
        __syncthreads();

        // combine halves, rescale O, write P to smem
#pragma unroll
        for (int ri = 0; ri < 2; ri++) {
            int rl = wm + ri*8 + g;
            float2 r0 = red[rl*2 + 0];
            float2 r1 = red[rl*2 + 1];
            float mold = mrun[ri];
            float mnew = fmaxf(mold, fmaxf(r0.x, r1.x));
            float corr = __expf(mold - mnew);
            lrun[ri] = lrun[ri] * corr
                     + r0.y * __expf(r0.x - mnew)
                     + r1.y * __expf(r1.x - mnew);
            mrun[ri] = mnew;
            float pscale = __expf(mh[ri] - mnew);
#pragma unroll
            for (int nt = 0; nt < 4; nt++) {
                oacc[nt][2*ri]   *= corr;
                oacc[nt][2*ri+1] *= corr;
                float p0 = tf32r(s[nt][2*ri]   * pscale);
                float p1 = tf32r(s[nt][2*ri+1] * pscale);
                *(float2*)&Ps[rl][wn*32 + nt*8 + 2*tg] = make_float2(p0, p1);
            }
        }
        __syncthreads();

        // O += P V   (warp tile 16 rows x 32 dims, k over 64 keys)
#pragma unroll
        for (int ks = 0; ks < 8; ks++) {
            uint32_t af[4], bf[4][2];
            af[0] = __float_as_uint(Ps[wm+g  ][ks*8+tg  ]);
            af[1] = __float_as_uint(Ps[wm+g+8][ks*8+tg  ]);
            af[2] = __float_as_uint(Ps[wm+g  ][ks*8+tg+4]);
            af[3] = __float_as_uint(Ps[wm+g+8][ks*8+tg+4]);
#pragma unroll
            for (int nt = 0; nt < 4; nt++) {
                bf[nt][0] = __float_as_uint(Vs[ks*8+tg  ][wn*32+nt*8+g]);
                bf[nt][1] = __float_as_uint(Vs[ks*8+tg+4][wn*32+nt*8+g]);
            }
#pragma unroll
            for (int nt = 0; nt < 4; nt++)
                mma_tf32(oacc[nt], af, bf[nt]);
        }
    }

    // epilogue: normalize + store
    float* obase = o + (size_t)(b * Tsz + q0) * Csz + h * HD;
#pragma unroll
    for (int ri = 0; ri < 2; ri++) {
        int rl = wm + ri*8 + g;
        float inv = 1.0f / lrun[ri];
#pragma unroll
        for (int nt = 0; nt < 4; nt++) {
            float2 r2 = make_float2(oacc[nt][2*ri] * inv, oacc[nt][2*ri+1] * inv);
            *(float2*)(obase + (size_t)rl * Csz + wn*32 + nt*8 + 2*tg) = r2;
        }
    }
}

// ---------------------------------------------------------------------------
extern "C" void kernel_launch(void* const* d_in, const int* in_sizes, int n_in,
                              void* d_out, int out_size)
{
    const float* x   = (const float*)d_in[0];
    const float* w_q = (const float*)d_in[1];
    const float* b_q = (const float*)d_in[2];
    const float* w_k = (const float*)d_in[3];
    const float* b_k = (const float*)d_in[4];
    const float* w_v = (const float*)d_in[5];
    const float* b_v = (const float*)d_in[6];
    const float* w_o = (const float*)d_in[7];
    const float* b_o = (const float*)d_in[8];
    float* out = (float*)d_out;

    float *q, *k, *v, *ao;
    cudaGetSymbolAddress((void**)&q,  g_q);
    cudaGetSymbolAddress((void**)&k,  g_k);
    cudaGetSymbolAddress((void**)&v,  g_v);
    cudaGetSymbolAddress((void**)&ao, g_ao);

    // projections (RoPE fused into Q and K epilogues)
    gemm_tf32<true ><<<dim3(Csz/64, Mrows/128), 256>>>(x, w_q, b_q, q, Mrows, Csz, Csz);
    gemm_tf32<true ><<<dim3(KVC/64, Mrows/128), 256>>>(x, w_k, b_k, k, Mrows, Csz, KVC);
    gemm_tf32<false><<<dim3(KVC/64, Mrows/128), 256>>>(x, w_v, b_v, v, Mrows, Csz, KVC);

    // flash attention (64 q-rows per CTA, 2 CTAs/SM)
    {
        int smem = (2*QB*68 + 2*64*72 + QB*4) * (int)sizeof(float);  // 72192
        cudaFuncSetAttribute(attn_tf32, cudaFuncAttributeMaxDynamicSharedMemorySize, smem);
        attn_tf32<<<dim3(Tsz/QB, NH, Bsz), 256, smem>>>(q, k, v, ao);
    }

    // output projection
    gemm_tf32<false><<<dim3(Csz/64, Mrows/128), 256>>>(ao, w_o, b_o, out, Mrows, Csz, Csz);
}

// round 6
// speedup vs baseline: 1.3712x; 1.3712x over previous
#include <cuda_runtime.h>
#include <cuda_fp16.h>
#include <math.h>
#include <stdint.h>

#define Bsz 2
#define Tsz 2048
#define Csz 1024
#define NH 16
#define NKV 4
#define HD 64
#define Mrows (Bsz*Tsz)      // 4096
#define KVC (NKV*HD)         // 256
#define QB 128               // q rows per attention CTA

// Scratch (device globals: no allocation allowed)
__device__ float g_q [Mrows*Csz];
__device__ float g_k [Mrows*KVC];
__device__ float g_v [Mrows*KVC];
__device__ float g_ao[Mrows*Csz];

__device__ __forceinline__ float tf32r(float x) {
    uint32_t u; asm("cvt.rna.tf32.f32 %0, %1;" : "=r"(u) : "f"(x));
    return __uint_as_float(u);
}

__device__ __forceinline__ void mma_tf32(float c[4], const uint32_t a[4], const uint32_t b[2]) {
    asm volatile(
        "mma.sync.aligned.m16n8k8.row.col.f32.tf32.tf32.f32 "
        "{%0,%1,%2,%3}, {%4,%5,%6,%7}, {%8,%9}, {%0,%1,%2,%3};\n"
        : "+f"(c[0]), "+f"(c[1]), "+f"(c[2]), "+f"(c[3])
        : "r"(a[0]), "r"(a[1]), "r"(a[2]), "r"(a[3]), "r"(b[0]), "r"(b[1]));
}

__device__ __forceinline__ void mma_f16(float c[4], const uint32_t a[4], const uint32_t b[2]) {
    asm volatile(
        "mma.sync.aligned.m16n8k16.row.col.f32.f16.f16.f32 "
        "{%0,%1,%2,%3}, {%4,%5,%6,%7}, {%8,%9}, {%0,%1,%2,%3};\n"
        : "+f"(c[0]), "+f"(c[1]), "+f"(c[2]), "+f"(c[3])
        : "r"(a[0]), "r"(a[1]), "r"(a[2]), "r"(a[3]), "r"(b[0]), "r"(b[1]));
}

__device__ __forceinline__ uint32_t packh2(float a, float b) {
    __half2 h = __floats2half2_rn(a, b);
    return *(uint32_t*)&h;
}

// ---------------------------------------------------------------------------
// tf32 tensor-core GEMM (unchanged from R4 — proven).
// ---------------------------------------------------------------------------
template<bool DO_ROPE>
__global__ __launch_bounds__(256)
void gemm_tf32(const float* __restrict__ A, const float* __restrict__ W,
               const float* __restrict__ bias, float* __restrict__ C,
               int M, int K, int N)
{
    __shared__ float As[16][136];
    __shared__ float Bs[16][72];

    int tid = threadIdx.x;
    int lane = tid & 31, w = tid >> 5;
    int g = lane >> 2, tg = lane & 3;
    int wm = (w & 3) * 32, wn = (w >> 2) * 32;
    int m0 = blockIdx.y * 128, n0 = blockIdx.x * 64;

    int ar0 = tid >> 2, ar1 = (tid + 256) >> 2, ac4 = tid & 3;
    int br  = tid >> 4, bc4 = tid & 15;

    float acc[2][4][4] = {};
    float4 areg0, areg1, breg;

    auto ldt = [&](int k0) {
        areg0 = *(const float4*)(A + (size_t)(m0 + ar0) * K + k0 + ac4 * 4);
        areg1 = *(const float4*)(A + (size_t)(m0 + ar1) * K + k0 + ac4 * 4);
        breg  = *(const float4*)(W + (size_t)(k0 + br) * N + n0 + bc4 * 4);
    };

    int niter = K / 16;
    ldt(0);

    for (int i = 0; i < niter; i++) {
        __syncthreads();
        As[ac4*4+0][ar0] = tf32r(areg0.x);
        As[ac4*4+1][ar0] = tf32r(areg0.y);
        As[ac4*4+2][ar0] = tf32r(areg0.z);
        As[ac4*4+3][ar0] = tf32r(areg0.w);
        As[ac4*4+0][ar1] = tf32r(areg1.x);
        As[ac4*4+1][ar1] = tf32r(areg1.y);
        As[ac4*4+2][ar1] = tf32r(areg1.z);
        As[ac4*4+3][ar1] = tf32r(areg1.w);
        {
            float4 u = make_float4(tf32r(breg.x), tf32r(breg.y),
                                   tf32r(breg.z), tf32r(breg.w));
            *(float4*)&Bs[br][bc4*4] = u;
        }
        __syncthreads();

        if (i + 1 < niter) ldt((i + 1) * 16);

#pragma unroll
        for (int ks = 0; ks < 2; ks++) {
            uint32_t af[2][4], bf[4][2];
#pragma unroll
            for (int mt = 0; mt < 2; mt++) {
                int mr = wm + mt * 16;
                af[mt][0] = __float_as_uint(As[ks*8+tg  ][mr+g  ]);
                af[mt][1] = __float_as_uint(As[ks*8+tg  ][mr+g+8]);
                af[mt][2] = __float_as_uint(As[ks*8+tg+4][mr+g  ]);
                af[mt][3] = __float_as_uint(As[ks*8+tg+4][mr+g+8]);
            }
#pragma unroll
            for (int nt = 0; nt < 4; nt++) {
                bf[nt][0] = __float_as_uint(Bs[ks*8+tg  ][wn+nt*8+g]);
                bf[nt][1] = __float_as_uint(Bs[ks*8+tg+4][wn+nt*8+g]);
            }
#pragma unroll
            for (int mt = 0; mt < 2; mt++)
#pragma unroll
                for (int nt = 0; nt < 4; nt++)
                    mma_tf32(acc[mt][nt], af[mt], bf[nt]);
        }
    }

#pragma unroll
    for (int mt = 0; mt < 2; mt++) {
        int r0 = m0 + wm + mt * 16 + g;
#pragma unroll
        for (int nt = 0; nt < 4; nt++) {
            int c = n0 + wn + nt * 8 + tg * 2;
            float2 bb = *(const float2*)(bias + c);
            float2 v0 = make_float2(acc[mt][nt][0] + bb.x, acc[mt][nt][1] + bb.y);
            float2 v1 = make_float2(acc[mt][nt][2] + bb.x, acc[mt][nt][3] + bb.y);
            if (DO_ROPE) {
                int pair = (c & (HD - 1)) >> 1;
                float inv = powf(10000.0f, -(float)(2 * pair) / (float)HD);
                float sn0, cs0, sn1, cs1;
                sincosf((float)(r0 & (Tsz - 1)) * inv, &sn0, &cs0);
                sincosf((float)((r0 + 8) & (Tsz - 1)) * inv, &sn1, &cs1);
                float e0 = v0.x, o0 = v0.y;
                v0.x = e0 * cs0 - o0 * sn0;  v0.y = e0 * sn0 + o0 * cs0;
                float e1 = v1.x, o1 = v1.y;
                v1.x = e1 * cs1 - o1 * sn1;  v1.y = e1 * sn1 + o1 * cs1;
            }
            *(float2*)(C + (size_t)r0 * N + c)       = v0;
            *(float2*)(C + (size_t)(r0 + 8) * N + c) = v1;
        }
    }
}

// ---------------------------------------------------------------------------
// Flash attention, fp16 tensor cores (m16n8k16), fp32 softmax/accumulators.
// CTA: 128 q-rows x 1 head, 256 threads, 8 warps = 4(m)x2(n), warp tile 32x32.
// Smem word (uint32=half2) layout, row stride 36 words -> all hot fragment
// LDS are bank-conflict-free. K/V register prefetch as in R4.
// ---------------------------------------------------------------------------
__global__ __launch_bounds__(256)
void attn_f16(const float* __restrict__ q, const float* __restrict__ k,
              const float* __restrict__ v, float* __restrict__ o)
{
    extern __shared__ uint32_t smu[];
    uint32_t (*Qs)[36] = (uint32_t(*)[36])smu;                    // [128][36] row=q-row, words over d
    uint32_t (*Ks)[36] = (uint32_t(*)[36])(smu + 128*36);         // [64][36]  row=key,   words over d
    uint32_t (*Vt)[36] = (uint32_t(*)[36])(smu + (128+64)*36);    // [64][36]  row=dim,   words over keys
    uint32_t (*Ps)[36] = (uint32_t(*)[36])(smu + (128+64+64)*36); // [128][36] row=q-row, words over keys
    float2*  red       = (float2*)(smu + (128+64+64+128)*36);     // [128][2]

    int b  = blockIdx.z;
    int h  = blockIdx.y;
    int qb = gridDim.x - 1 - blockIdx.x;   // heavy blocks first
    int q0 = qb * QB;
    int kvh = h >> 2;

    int tid = threadIdx.x;
    int lane = tid & 31, w = tid >> 5;
    int g = lane >> 2, tg = lane & 3;
    int wm = (w >> 1) * 32;    // warp row origin (0,32,64,96)
    int wn = w & 1;            // warp col half

    // load Q tile (pre-scaled by 1/8, fp16)
    {
        const float* qbase = q + (size_t)(b * Tsz + q0) * Csz + h * HD;
#pragma unroll
        for (int p = 0; p < 8; p++) {
            int i4 = tid + p * 256;
            int r = i4 >> 4, c4 = i4 & 15;
            float4 t = *(const float4*)(qbase + (size_t)r * Csz + c4 * 4);
            uint2 u = make_uint2(packh2(t.x * 0.125f, t.y * 0.125f),
                                 packh2(t.z * 0.125f, t.w * 0.125f));
            *(uint2*)&Qs[r][c4*2] = u;
        }
    }

    float mrun[2][2], lrun[2][2];
    float oacc[2][4][4] = {};
#pragma unroll
    for (int mt = 0; mt < 2; mt++)
#pragma unroll
        for (int ri = 0; ri < 2; ri++) { mrun[mt][ri] = -1e30f; lrun[mt][ri] = 0.f; }

    // prefetch registers: K 4 float4 (key=idx>>4, c4=idx&15), V 2 tasks x 2 rows
    float4 kreg[4], vreg[4];
    auto ldkv = [&](int kb) {
        const float* kp = k + (size_t)(b * Tsz + kb * 64) * KVC + kvh * HD;
        const float* vp = v + (size_t)(b * Tsz + kb * 64) * KVC + kvh * HD;
#pragma unroll
        for (int p = 0; p < 4; p++) {
            int idx = tid + p * 256;
            int key = idx >> 4, c4 = idx & 15;
            kreg[p] = *(const float4*)(kp + (size_t)key * KVC + c4 * 4);
        }
#pragma unroll
        for (int p = 0; p < 2; p++) {
            int idx = tid + p * 256;           // 0..511
            int k2 = idx & 31, c4 = idx >> 5;  // key pair, dim chunk
            vreg[p*2+0] = *(const float4*)(vp + (size_t)(2*k2  ) * KVC + c4 * 4);
            vreg[p*2+1] = *(const float4*)(vp + (size_t)(2*k2+1) * KVC + c4 * 4);
        }
    };

    int kb_max = 2 * qb + 1;
    ldkv(0);

    for (int kb = 0; kb <= kb_max; kb++) {
        __syncthreads();   // Qs ready (first iter) / Ks,Vt,Ps consumed (later)
        // stage K (key-major halves)
#pragma unroll
        for (int p = 0; p < 4; p++) {
            int idx = tid + p * 256;
            int key = idx >> 4, c4 = idx & 15;
            uint2 u = make_uint2(packh2(kreg[p].x, kreg[p].y),
                                 packh2(kreg[p].z, kreg[p].w));
            *(uint2*)&Ks[key][c4*2] = u;
        }
        // stage V transposed (dim-major, half2 packs key pair)
#pragma unroll
        for (int p = 0; p < 2; p++) {
            int idx = tid + p * 256;
            int k2 = idx & 31, c4 = idx >> 5;
            float4 v0 = vreg[p*2+0], v1 = vreg[p*2+1];
            Vt[c4*4+0][k2] = packh2(v0.x, v1.x);
            Vt[c4*4+1][k2] = packh2(v0.y, v1.y);
            Vt[c4*4+2][k2] = packh2(v0.z, v1.z);
            Vt[c4*4+3][k2] = packh2(v0.w, v1.w);
        }
        __syncthreads();

        if (kb < kb_max) ldkv(kb + 1);   // overlap next tile's LDGs

        // S = Q K^T  (4 k16-slices over d=64)
        float s[2][4][4] = {};
#pragma unroll
        for (int ks = 0; ks < 4; ks++) {
            uint32_t af[2][4], bf[4][2];
#pragma unroll
            for (int mt = 0; mt < 2; mt++) {
                int mr = wm + mt * 16;
                af[mt][0] = Qs[mr+g  ][ks*8+tg  ];
                af[mt][1] = Qs[mr+g+8][ks*8+tg  ];
                af[mt][2] = Qs[mr+g  ][ks*8+tg+4];
                af[mt][3] = Qs[mr+g+8][ks*8+tg+4];
            }
#pragma unroll
            for (int nt = 0; nt < 4; nt++) {
                int key = wn*32 + nt*8 + g;
                bf[nt][0] = Ks[key][ks*8+tg  ];
                bf[nt][1] = Ks[key][ks*8+tg+4];
            }
#pragma unroll
            for (int mt = 0; mt < 2; mt++)
#pragma unroll
                for (int nt = 0; nt < 4; nt++)
                    mma_f16(s[mt][nt], af[mt], bf[nt]);
        }

        // causal mask (only near the diagonal)
        if (kb >= 2 * qb) {
#pragma unroll
            for (int mt = 0; mt < 2; mt++) {
                int row0 = q0 + wm + mt * 16 + g;
#pragma unroll
                for (int nt = 0; nt < 4; nt++) {
                    int col = kb * 64 + wn * 32 + nt * 8 + 2 * tg;
                    if (col     > row0    ) s[mt][nt][0] = -1e30f;
                    if (col + 1 > row0    ) s[mt][nt][1] = -1e30f;
                    if (col     > row0 + 8) s[mt][nt][2] = -1e30f;
                    if (col + 1 > row0 + 8) s[mt][nt][3] = -1e30f;
                }
            }
        }

        // per-warp-half row max + exp + sum
        float mh[2][2], sh[2][2];
#pragma unroll
        for (int mt = 0; mt < 2; mt++)
#pragma unroll
            for (int ri = 0; ri < 2; ri++) {
                float mx = -1e30f;
#pragma unroll
                for (int nt = 0; nt < 4; nt++) {
                    mx = fmaxf(mx, s[mt][nt][2*ri]);
                    mx = fmaxf(mx, s[mt][nt][2*ri+1]);
                }
                mx = fmaxf(mx, __shfl_xor_sync(0xffffffffu, mx, 1));
                mx = fmaxf(mx, __shfl_xor_sync(0xffffffffu, mx, 2));
                float sum = 0.f;
#pragma unroll
                for (int nt = 0; nt < 4; nt++) {
                    float p0 = __expf(s[mt][nt][2*ri]   - mx);
                    float p1 = __expf(s[mt][nt][2*ri+1] - mx);
                    s[mt][nt][2*ri] = p0; s[mt][nt][2*ri+1] = p1;
                    sum += p0 + p1;
                }
                sum += __shfl_xor_sync(0xffffffffu, sum, 1);
                sum += __shfl_xor_sync(0xffffffffu, sum, 2);
                mh[mt][ri] = mx; sh[mt][ri] = sum;
            }

        if (tg == 0) {
#pragma unroll
            for (int mt = 0; mt < 2; mt++)
#pragma unroll
                for (int ri = 0; ri < 2; ri++)
                    red[(wm + mt*16 + ri*8 + g) * 2 + wn] = make_float2(mh[mt][ri], sh[mt][ri]);
        }
        __syncthreads();

        // combine halves, rescale O, write P (fp16) to smem
#pragma unroll
        for (int mt = 0; mt < 2; mt++)
#pragma unroll
            for (int ri = 0; ri < 2; ri++) {
                int rl = wm + mt*16 + ri*8 + g;
                float2 r0 = red[rl*2 + 0];
                float2 r1 = red[rl*2 + 1];
                float mold = mrun[mt][ri];
                float mnew = fmaxf(mold, fmaxf(r0.x, r1.x));
                float corr = __expf(mold - mnew);
                lrun[mt][ri] = lrun[mt][ri] * corr
                             + r0.y * __expf(r0.x - mnew)
                             + r1.y * __expf(r1.x - mnew);
                mrun[mt][ri] = mnew;
                float pscale = __expf(mh[mt][ri] - mnew);
#pragma unroll
                for (int nt = 0; nt < 4; nt++) {
                    oacc[mt][nt][2*ri]   *= corr;
                    oacc[mt][nt][2*ri+1] *= corr;
                    Ps[rl][wn*16 + nt*4 + tg] =
                        packh2(s[mt][nt][2*ri] * pscale, s[mt][nt][2*ri+1] * pscale);
                }
            }
        __syncthreads();

        // O += P V   (4 k16-slices over 64 keys)
#pragma unroll
        for (int ks = 0; ks < 4; ks++) {
            uint32_t af[2][4], bf[4][2];
#pragma unroll
            for (int mt = 0; mt < 2; mt++) {
                int mr = wm + mt * 16;
                af[mt][0] = Ps[mr+g  ][ks*8+tg  ];
                af[mt][1] = Ps[mr+g+8][ks*8+tg  ];
                af[mt][2] = Ps[mr+g  ][ks*8+tg+4];
                af[mt][3] = Ps[mr+g+8][ks*8+tg+4];
            }
#pragma unroll
            for (int nt = 0; nt < 4; nt++) {
                int dim = wn*32 + nt*8 + g;
                bf[nt][0] = Vt[dim][ks*8+tg  ];
                bf[nt][1] = Vt[dim][ks*8+tg+4];
            }
#pragma unroll
            for (int mt = 0; mt < 2; mt++)
#pragma unroll
                for (int nt = 0; nt < 4; nt++)
                    mma_f16(oacc[mt][nt], af[mt], bf[nt]);
        }
    }

    // epilogue: normalize + store. NOTE: PV computed D = P@V with output cols
    // owned as (n=dim) -> oacc[mt][nt] row rl, dim wn*32+nt*8+2tg(+1)
    float* obase = o + (size_t)(b * Tsz + q0) * Csz + h * HD;
#pragma unroll
    for (int mt = 0; mt < 2; mt++)
#pragma unroll
        for (int ri = 0; ri < 2; ri++) {
            int rl = wm + mt*16 + ri*8 + g;
            float inv = 1.0f / lrun[mt][ri];
#pragma unroll
            for (int nt = 0; nt < 4; nt++) {
                float2 r2 = make_float2(oacc[mt][nt][2*ri] * inv, oacc[mt][nt][2*ri+1] * inv);
                *(float2*)(obase + (size_t)rl * Csz + wn*32 + nt*8 + 2*tg) = r2;
            }
        }
}

// ---------------------------------------------------------------------------
extern "C" void kernel_launch(void* const* d_in, const int* in_sizes, int n_in,
                              void* d_out, int out_size)
{
    const float* x   = (const float*)d_in[0];
    const float* w_q = (const float*)d_in[1];
    const float* b_q = (const float*)d_in[2];
    const float* w_k = (const float*)d_in[3];
    const float* b_k = (const float*)d_in[4];
    const float* w_v = (const float*)d_in[5];
    const float* b_v = (const float*)d_in[6];
    const float* w_o = (const float*)d_in[7];
    const float* b_o = (const float*)d_in[8];
    float* out = (float*)d_out;

    float *q, *k, *v, *ao;
    cudaGetSymbolAddress((void**)&q,  g_q);
    cudaGetSymbolAddress((void**)&k,  g_k);
    cudaGetSymbolAddress((void**)&v,  g_v);
    cudaGetSymbolAddress((void**)&ao, g_ao);

    // projections (RoPE fused into Q and K epilogues)
    gemm_tf32<true ><<<dim3(Csz/64, Mrows/128), 256>>>(x, w_q, b_q, q, Mrows, Csz, Csz);
    gemm_tf32<true ><<<dim3(KVC/64, Mrows/128), 256>>>(x, w_k, b_k, k, Mrows, Csz, KVC);
    gemm_tf32<false><<<dim3(KVC/64, Mrows/128), 256>>>(x, w_v, b_v, v, Mrows, Csz, KVC);

    // flash attention (fp16 tensor cores, 128 q-rows per CTA)
    {
        int smem = (128+64+64+128) * 36 * 4 + 128 * 2 * 8;   // 55296 + 2048 = 57344
        cudaFuncSetAttribute(attn_f16, cudaFuncAttributeMaxDynamicSharedMemorySize, smem);
        attn_f16<<<dim3(Tsz/QB, NH, Bsz), 256, smem>>>(q, k, v, ao);
    }

    // output projection
    gemm_tf32<false><<<dim3(Csz/64, Mrows/128), 256>>>(ao, w_o, b_o, out, Mrows, Csz, Csz);
}

// round 7
// speedup vs baseline: 1.3954x; 1.0176x over previous
#include <cuda_runtime.h>
#include <cuda_fp16.h>
#include <math.h>
#include <stdint.h>

#define Bsz 2
#define Tsz 2048
#define Csz 1024
#define NH 16
#define NKV 4
#define HD 64
#define Mrows (Bsz*Tsz)      // 4096
#define KVC (NKV*HD)         // 256
#define QB 128               // q rows per attention CTA

// Scratch (device globals: no allocation allowed)
__device__ float g_q [Mrows*Csz];
__device__ float g_k [Mrows*KVC];
__device__ float g_v [Mrows*KVC];
__device__ float g_ao[Mrows*Csz];

__device__ __forceinline__ float tf32r(float x) {
    uint32_t u; asm("cvt.rna.tf32.f32 %0, %1;" : "=r"(u) : "f"(x));
    return __uint_as_float(u);
}

__device__ __forceinline__ void mma_tf32(float c[4], const uint32_t a[4], const uint32_t b[2]) {
    asm volatile(
        "mma.sync.aligned.m16n8k8.row.col.f32.tf32.tf32.f32 "
        "{%0,%1,%2,%3}, {%4,%5,%6,%7}, {%8,%9}, {%0,%1,%2,%3};\n"
        : "+f"(c[0]), "+f"(c[1]), "+f"(c[2]), "+f"(c[3])
        : "r"(a[0]), "r"(a[1]), "r"(a[2]), "r"(a[3]), "r"(b[0]), "r"(b[1]));
}

__device__ __forceinline__ void mma_f16(float c[4], const uint32_t a[4], const uint32_t b[2]) {
    asm volatile(
        "mma.sync.aligned.m16n8k16.row.col.f32.f16.f16.f32 "
        "{%0,%1,%2,%3}, {%4,%5,%6,%7}, {%8,%9}, {%0,%1,%2,%3};\n"
        : "+f"(c[0]), "+f"(c[1]), "+f"(c[2]), "+f"(c[3])
        : "r"(a[0]), "r"(a[1]), "r"(a[2]), "r"(a[3]), "r"(b[0]), "r"(b[1]));
}

__device__ __forceinline__ uint32_t packh2(float a, float b) {
    __half2 h = __floats2half2_rn(a, b);
    return *(uint32_t*)&h;
}

#define LDSM4(r0, r1, r2, r3, addr) \
    asm volatile("ldmatrix.sync.aligned.m8n8.x4.shared.b16 {%0,%1,%2,%3}, [%4];" \
        : "=r"(r0), "=r"(r1), "=r"(r2), "=r"(r3) : "r"(addr))

// ---------------------------------------------------------------------------
// tf32 tensor-core GEMM (unchanged — proven at 627/512us rounds).
// ---------------------------------------------------------------------------
template<bool DO_ROPE>
__global__ __launch_bounds__(256)
void gemm_tf32(const float* __restrict__ A, const float* __restrict__ W,
               const float* __restrict__ bias, float* __restrict__ C,
               int M, int K, int N)
{
    __shared__ float As[16][136];
    __shared__ float Bs[16][72];

    int tid = threadIdx.x;
    int lane = tid & 31, w = tid >> 5;
    int g = lane >> 2, tg = lane & 3;
    int wm = (w & 3) * 32, wn = (w >> 2) * 32;
    int m0 = blockIdx.y * 128, n0 = blockIdx.x * 64;

    int ar0 = tid >> 2, ar1 = (tid + 256) >> 2, ac4 = tid & 3;
    int br  = tid >> 4, bc4 = tid & 15;

    float acc[2][4][4] = {};
    float4 areg0, areg1, breg;

    auto ldt = [&](int k0) {
        areg0 = *(const float4*)(A + (size_t)(m0 + ar0) * K + k0 + ac4 * 4);
        areg1 = *(const float4*)(A + (size_t)(m0 + ar1) * K + k0 + ac4 * 4);
        breg  = *(const float4*)(W + (size_t)(k0 + br) * N + n0 + bc4 * 4);
    };

    int niter = K / 16;
    ldt(0);

    for (int i = 0; i < niter; i++) {
        __syncthreads();
        As[ac4*4+0][ar0] = tf32r(areg0.x);
        As[ac4*4+1][ar0] = tf32r(areg0.y);
        As[ac4*4+2][ar0] = tf32r(areg0.z);
        As[ac4*4+3][ar0] = tf32r(areg0.w);
        As[ac4*4+0][ar1] = tf32r(areg1.x);
        As[ac4*4+1][ar1] = tf32r(areg1.y);
        As[ac4*4+2][ar1] = tf32r(areg1.z);
        As[ac4*4+3][ar1] = tf32r(areg1.w);
        {
            float4 u = make_float4(tf32r(breg.x), tf32r(breg.y),
                                   tf32r(breg.z), tf32r(breg.w));
            *(float4*)&Bs[br][bc4*4] = u;
        }
        __syncthreads();

        if (i + 1 < niter) ldt((i + 1) * 16);

#pragma unroll
        for (int ks = 0; ks < 2; ks++) {
            uint32_t af[2][4], bf[4][2];
#pragma unroll
            for (int mt = 0; mt < 2; mt++) {
                int mr = wm + mt * 16;
                af[mt][0] = __float_as_uint(As[ks*8+tg  ][mr+g  ]);
                af[mt][1] = __float_as_uint(As[ks*8+tg  ][mr+g+8]);
                af[mt][2] = __float_as_uint(As[ks*8+tg+4][mr+g  ]);
                af[mt][3] = __float_as_uint(As[ks*8+tg+4][mr+g+8]);
            }
#pragma unroll
            for (int nt = 0; nt < 4; nt++) {
                bf[nt][0] = __float_as_uint(Bs[ks*8+tg  ][wn+nt*8+g]);
                bf[nt][1] = __float_as_uint(Bs[ks*8+tg+4][wn+nt*8+g]);
            }
#pragma unroll
            for (int mt = 0; mt < 2; mt++)
#pragma unroll
                for (int nt = 0; nt < 4; nt++)
                    mma_tf32(acc[mt][nt], af[mt], bf[nt]);
        }
    }

#pragma unroll
    for (int mt = 0; mt < 2; mt++) {
        int r0 = m0 + wm + mt * 16 + g;
#pragma unroll
        for (int nt = 0; nt < 4; nt++) {
            int c = n0 + wn + nt * 8 + tg * 2;
            float2 bb = *(const float2*)(bias + c);
            float2 v0 = make_float2(acc[mt][nt][0] + bb.x, acc[mt][nt][1] + bb.y);
            float2 v1 = make_float2(acc[mt][nt][2] + bb.x, acc[mt][nt][3] + bb.y);
            if (DO_ROPE) {
                int pair = (c & (HD - 1)) >> 1;
                float inv = powf(10000.0f, -(float)(2 * pair) / (float)HD);
                float sn0, cs0, sn1, cs1;
                sincosf((float)(r0 & (Tsz - 1)) * inv, &sn0, &cs0);
                sincosf((float)((r0 + 8) & (Tsz - 1)) * inv, &sn1, &cs1);
                float e0 = v0.x, o0 = v0.y;
                v0.x = e0 * cs0 - o0 * sn0;  v0.y = e0 * sn0 + o0 * cs0;
                float e1 = v1.x, o1 = v1.y;
                v1.x = e1 * cs1 - o1 * sn1;  v1.y = e1 * sn1 + o1 * cs1;
            }
            *(float2*)(C + (size_t)r0 * N + c)       = v0;
            *(float2*)(C + (size_t)(r0 + 8) * N + c) = v1;
        }
    }
}

// ---------------------------------------------------------------------------
// Flash attention, fp16 tensor cores + ldmatrix fragment loads.
// CTA: 128 q-rows x 1 head, 256 threads, 8 warps = 4(m)x2(n), warp tile 32x32.
// Row stride 36 words: LDSM 16B row-granules land on distinct bank quads.
// ---------------------------------------------------------------------------
__global__ __launch_bounds__(256)
void attn_f16(const float* __restrict__ q, const float* __restrict__ k,
              const float* __restrict__ v, float* __restrict__ o)
{
    extern __shared__ uint32_t smu[];
    uint32_t (*Qs)[36] = (uint32_t(*)[36])smu;                    // [128][36] row=q-row, words over d
    uint32_t (*Ks)[36] = (uint32_t(*)[36])(smu + 128*36);         // [64][36]  row=key,   words over d
    uint32_t (*Vt)[36] = (uint32_t(*)[36])(smu + (128+64)*36);    // [64][36]  row=dim,   words over keys
    uint32_t (*Ps)[36] = (uint32_t(*)[36])(smu + (128+64+64)*36); // [128][36] row=q-row, words over keys
    float2*  red       = (float2*)(smu + (128+64+64+128)*36);     // [128][2]

    int b  = blockIdx.z;
    int h  = blockIdx.y;
    int qb = gridDim.x - 1 - blockIdx.x;   // heavy blocks first
    int q0 = qb * QB;
    int kvh = h >> 2;

    int tid = threadIdx.x;
    int lane = tid & 31, w = tid >> 5;
    int g = lane >> 2, tg = lane & 3;
    int wm = (w >> 1) * 32;    // warp row origin (0,32,64,96)
    int wn = w & 1;            // warp col half

    // ldmatrix per-lane geometry
    int la = lane & 15;                           // A-frag row offset
    int ha = (lane >> 4) * 4;                     // A-frag word offset (+4 for k-high)
    int lb = (lane & 7) + (lane >> 4) * 8;        // B-frag row offset
    int hb = ((lane >> 3) & 1) * 4;               // B-frag word offset

    uint32_t qsb = (uint32_t)__cvta_generic_to_shared(&Qs[0][0]);
    uint32_t ksb = (uint32_t)__cvta_generic_to_shared(&Ks[0][0]);
    uint32_t vtb = (uint32_t)__cvta_generic_to_shared(&Vt[0][0]);
    uint32_t psb = (uint32_t)__cvta_generic_to_shared(&Ps[0][0]);

    // load Q tile (pre-scaled by 1/8, fp16)
    {
        const float* qbase = q + (size_t)(b * Tsz + q0) * Csz + h * HD;
#pragma unroll
        for (int p = 0; p < 8; p++) {
            int i4 = tid + p * 256;
            int r = i4 >> 4, c4 = i4 & 15;
            float4 t = *(const float4*)(qbase + (size_t)r * Csz + c4 * 4);
            uint2 u = make_uint2(packh2(t.x * 0.125f, t.y * 0.125f),
                                 packh2(t.z * 0.125f, t.w * 0.125f));
            *(uint2*)&Qs[r][c4*2] = u;
        }
    }

    float mrun[2][2], lrun[2][2];
    float oacc[2][4][4] = {};
#pragma unroll
    for (int mt = 0; mt < 2; mt++)
#pragma unroll
        for (int ri = 0; ri < 2; ri++) { mrun[mt][ri] = -1e30f; lrun[mt][ri] = 0.f; }

    float4 kreg[4], vreg[4];
    auto ldkv = [&](int kb) {
        const float* kp = k + (size_t)(b * Tsz + kb * 64) * KVC + kvh * HD;
        const float* vp = v + (size_t)(b * Tsz + kb * 64) * KVC + kvh * HD;
#pragma unroll
        for (int p = 0; p < 4; p++) {
            int idx = tid + p * 256;
            int key = idx >> 4, c4 = idx & 15;
            kreg[p] = *(const float4*)(kp + (size_t)key * KVC + c4 * 4);
        }
#pragma unroll
        for (int p = 0; p < 2; p++) {
            int idx = tid + p * 256;           // 0..511
            int k2 = idx & 31, c4 = idx >> 5;  // key pair, dim chunk
            vreg[p*2+0] = *(const float4*)(vp + (size_t)(2*k2  ) * KVC + c4 * 4);
            vreg[p*2+1] = *(const float4*)(vp + (size_t)(2*k2+1) * KVC + c4 * 4);
        }
    };

    int kb_max = 2 * qb + 1;
    ldkv(0);

    for (int kb = 0; kb <= kb_max; kb++) {
        __syncthreads();   // Qs ready (first iter) / Ks,Vt,Ps consumed (later)
        // stage K (key-major halves)
#pragma unroll
        for (int p = 0; p < 4; p++) {
            int idx = tid + p * 256;
            int key = idx >> 4, c4 = idx & 15;
            uint2 u = make_uint2(packh2(kreg[p].x, kreg[p].y),
                                 packh2(kreg[p].z, kreg[p].w));
            *(uint2*)&Ks[key][c4*2] = u;
        }
        // stage V transposed (dim-major, half2 packs key pair)
#pragma unroll
        for (int p = 0; p < 2; p++) {
            int idx = tid + p * 256;
            int k2 = idx & 31, c4 = idx >> 5;
            float4 v0 = vreg[p*2+0], v1 = vreg[p*2+1];
            Vt[c4*4+0][k2] = packh2(v0.x, v1.x);
            Vt[c4*4+1][k2] = packh2(v0.y, v1.y);
            Vt[c4*4+2][k2] = packh2(v0.z, v1.z);
            Vt[c4*4+3][k2] = packh2(v0.w, v1.w);
        }
        __syncthreads();

        if (kb < kb_max) ldkv(kb + 1);   // overlap next tile's LDGs

        // S = Q K^T  (4 k16-slices over d=64), fragments via ldmatrix
        float s[2][4][4] = {};
#pragma unroll
        for (int ks = 0; ks < 4; ks++) {
            uint32_t af[2][4], bf[4][2];
#pragma unroll
            for (int mt = 0; mt < 2; mt++) {
                uint32_t addr = qsb + ((wm + mt*16 + la) * 36 + ks*8 + ha) * 4;
                LDSM4(af[mt][0], af[mt][1], af[mt][2], af[mt][3], addr);
            }
#pragma unroll
            for (int ntp = 0; ntp < 2; ntp++) {
                uint32_t addr = ksb + ((wn*32 + ntp*16 + lb) * 36 + ks*8 + hb) * 4;
                LDSM4(bf[2*ntp][0], bf[2*ntp][1], bf[2*ntp+1][0], bf[2*ntp+1][1], addr);
            }
#pragma unroll
            for (int mt = 0; mt < 2; mt++)
#pragma unroll
                for (int nt = 0; nt < 4; nt++)
                    mma_f16(s[mt][nt], af[mt], bf[nt]);
        }

        // causal mask (only near the diagonal)
        if (kb >= 2 * qb) {
#pragma unroll
            for (int mt = 0; mt < 2; mt++) {
                int row0 = q0 + wm + mt * 16 + g;
#pragma unroll
                for (int nt = 0; nt < 4; nt++) {
                    int col = kb * 64 + wn * 32 + nt * 8 + 2 * tg;
                    if (col     > row0    ) s[mt][nt][0] = -1e30f;
                    if (col + 1 > row0    ) s[mt][nt][1] = -1e30f;
                    if (col     > row0 + 8) s[mt][nt][2] = -1e30f;
                    if (col + 1 > row0 + 8) s[mt][nt][3] = -1e30f;
                }
            }
        }

        // per-warp-half row max + exp + sum
        float mh[2][2], sh[2][2];
#pragma unroll
        for (int mt = 0; mt < 2; mt++)
#pragma unroll
            for (int ri = 0; ri < 2; ri++) {
                float mx = -1e30f;
#pragma unroll
                for (int nt = 0; nt < 4; nt++) {
                    mx = fmaxf(mx, s[mt][nt][2*ri]);
                    mx = fmaxf(mx, s[mt][nt][2*ri+1]);
                }
                mx = fmaxf(mx, __shfl_xor_sync(0xffffffffu, mx, 1));
                mx = fmaxf(mx, __shfl_xor_sync(0xffffffffu, mx, 2));
                float sum = 0.f;
#pragma unroll
                for (int nt = 0; nt < 4; nt++) {
                    float p0 = __expf(s[mt][nt][2*ri]   - mx);
                    float p1 = __expf(s[mt][nt][2*ri+1] - mx);
                    s[mt][nt][2*ri] = p0; s[mt][nt][2*ri+1] = p1;
                    sum += p0 + p1;
                }
                sum += __shfl_xor_sync(0xffffffffu, sum, 1);
                sum += __shfl_xor_sync(0xffffffffu, sum, 2);
                mh[mt][ri] = mx; sh[mt][ri] = sum;
            }

        if (tg == 0) {
#pragma unroll
            for (int mt = 0; mt < 2; mt++)
#pragma unroll
                for (int ri = 0; ri < 2; ri++)
                    red[(wm + mt*16 + ri*8 + g) * 2 + wn] = make_float2(mh[mt][ri], sh[mt][ri]);
        }
        __syncthreads();

        // combine halves, rescale O, write P (fp16) to smem
#pragma unroll
        for (int mt = 0; mt < 2; mt++)
#pragma unroll
            for (int ri = 0; ri < 2; ri++) {
                int rl = wm + mt*16 + ri*8 + g;
                float2 r0 = red[rl*2 + 0];
                float2 r1 = red[rl*2 + 1];
                float mold = mrun[mt][ri];
                float mnew = fmaxf(mold, fmaxf(r0.x, r1.x));
                float corr = __expf(mold - mnew);
                lrun[mt][ri] = lrun[mt][ri] * corr
                             + r0.y * __expf(r0.x - mnew)
                             + r1.y * __expf(r1.x - mnew);
                mrun[mt][ri] = mnew;
                float pscale = __expf(mh[mt][ri] - mnew);
#pragma unroll
                for (int nt = 0; nt < 4; nt++) {
                    oacc[mt][nt][2*ri]   *= corr;
                    oacc[mt][nt][2*ri+1] *= corr;
                    Ps[rl][wn*16 + nt*4 + tg] =
                        packh2(s[mt][nt][2*ri] * pscale, s[mt][nt][2*ri+1] * pscale);
                }
            }
        __syncthreads();

        // O += P V   (4 k16-slices over 64 keys), fragments via ldmatrix
#pragma unroll
        for (int ks = 0; ks < 4; ks++) {
            uint32_t af[2][4], bf[4][2];
#pragma unroll
            for (int mt = 0; mt < 2; mt++) {
                uint32_t addr = psb + ((wm + mt*16 + la) * 36 + ks*8 + ha) * 4;
                LDSM4(af[mt][0], af[mt][1], af[mt][2], af[mt][3], addr);
            }
#pragma unroll
            for (int ntp = 0; ntp < 2; ntp++) {
                uint32_t addr = vtb + ((wn*32 + ntp*16 + lb) * 36 + ks*8 + hb) * 4;
                LDSM4(bf[2*ntp][0], bf[2*ntp][1], bf[2*ntp+1][0], bf[2*ntp+1][1], addr);
            }
#pragma unroll
            for (int mt = 0; mt < 2; mt++)
#pragma unroll
                for (int nt = 0; nt < 4; nt++)
                    mma_f16(oacc[mt][nt], af[mt], bf[nt]);
        }
    }

    // epilogue: normalize + store
    float* obase = o + (size_t)(b * Tsz + q0) * Csz + h * HD;
#pragma unroll
    for (int mt = 0; mt < 2; mt++)
#pragma unroll
        for (int ri = 0; ri < 2; ri++) {
            int rl = wm + mt*16 + ri*8 + g;
            float inv = 1.0f / lrun[mt][ri];
#pragma unroll
            for (int nt = 0; nt < 4; nt++) {
                float2 r2 = make_float2(oacc[mt][nt][2*ri] * inv, oacc[mt][nt][2*ri+1] * inv);
                *(float2*)(obase + (size_t)rl * Csz + wn*32 + nt*8 + 2*tg) = r2;
            }
        }
}

// ---------------------------------------------------------------------------
extern "C" void kernel_launch(void* const* d_in, const int* in_sizes, int n_in,
                              void* d_out, int out_size)
{
    const float* x   = (const float*)d_in[0];
    const float* w_q = (const float*)d_in[1];
    const float* b_q = (const float*)d_in[2];
    const float* w_k = (const float*)d_in[3];
    const float* b_k = (const float*)d_in[4];
    const float* w_v = (const float*)d_in[5];
    const float* b_v = (const float*)d_in[6];
    const float* w_o = (const float*)d_in[7];
    const float* b_o = (const float*)d_in[8];
    float* out = (float*)d_out;

    float *q, *k, *v, *ao;
    cudaGetSymbolAddress((void**)&q,  g_q);
    cudaGetSymbolAddress((void**)&k,  g_k);
    cudaGetSymbolAddress((void**)&v,  g_v);
    cudaGetSymbolAddress((void**)&ao, g_ao);

    // projections (RoPE fused into Q and K epilogues)
    gemm_tf32<true ><<<dim3(Csz/64, Mrows/128), 256>>>(x, w_q, b_q, q, Mrows, Csz, Csz);
    gemm_tf32<true ><<<dim3(KVC/64, Mrows/128), 256>>>(x, w_k, b_k, k, Mrows, Csz, KVC);
    gemm_tf32<false><<<dim3(KVC/64, Mrows/128), 256>>>(x, w_v, b_v, v, Mrows, Csz, KVC);

    // flash attention (fp16 tensor cores + ldmatrix, 128 q-rows per CTA)
    {
        int smem = (128+64+64+128) * 36 * 4 + 128 * 2 * 8;   // 57344
        cudaFuncSetAttribute(attn_f16, cudaFuncAttributeMaxDynamicSharedMemorySize, smem);
        attn_f16<<<dim3(Tsz/QB, NH, Bsz), 256, smem>>>(q, k, v, ao);
    }

    // output projection
    gemm_tf32<false><<<dim3(Csz/64, Mrows/128), 256>>>(ao, w_o, b_o, out, Mrows, Csz, Csz);
}

// round 8
// speedup vs baseline: 2.1222x; 1.5208x over previous
#include <cuda_runtime.h>
#include <cuda_fp16.h>
#include <math.h>
#include <stdint.h>

#define Bsz 2
#define Tsz 2048
#define Csz 1024
#define NH 16
#define NKV 4
#define HD 64
#define Mrows (Bsz*Tsz)      // 4096
#define KVC (NKV*HD)         // 256
#define QB 128               // q rows per attention CTA

// Scratch (device globals: no allocation allowed)
__device__ float g_q [Mrows*Csz];
__device__ float g_k [Mrows*KVC];
__device__ float g_v [Mrows*KVC];
__device__ float g_ao[Mrows*Csz];

__device__ __forceinline__ void mma_f16(float c[4], const uint32_t a[4], const uint32_t b[2]) {
    asm volatile(
        "mma.sync.aligned.m16n8k16.row.col.f32.f16.f16.f32 "
        "{%0,%1,%2,%3}, {%4,%5,%6,%7}, {%8,%9}, {%0,%1,%2,%3};\n"
        : "+f"(c[0]), "+f"(c[1]), "+f"(c[2]), "+f"(c[3])
        : "r"(a[0]), "r"(a[1]), "r"(a[2]), "r"(a[3]), "r"(b[0]), "r"(b[1]));
}

__device__ __forceinline__ uint32_t packh2(float a, float b) {
    __half2 h = __floats2half2_rn(a, b);
    return *(uint32_t*)&h;
}

#define LDSM4(r0, r1, r2, r3, addr) \
    asm volatile("ldmatrix.sync.aligned.m8n8.x4.shared.b16 {%0,%1,%2,%3}, [%4];" \
        : "=r"(r0), "=r"(r1), "=r"(r2), "=r"(r3) : "r"(addr))

#define LDSM4T(r0, r1, r2, r3, addr) \
    asm volatile("ldmatrix.sync.aligned.m8n8.x4.trans.shared.b16 {%0,%1,%2,%3}, [%4];" \
        : "=r"(r0), "=r"(r1), "=r"(r2), "=r"(r3) : "r"(addr))

// ---------------------------------------------------------------------------
// fp16 tensor-core GEMM: C[M,N] = A[M,K] @ W[K,N] + bias (+ fused RoPE).
// Block 128x64, BK=32, 8 warps 4(m)x2(n), warp tile 32x32, m16n8k16 mma.
// A fragments: ldmatrix on row-major As. B fragments: ldmatrix.trans on
// k-major Bs (W's native layout -> no staging transpose).
// ---------------------------------------------------------------------------
template<bool DO_ROPE>
__global__ __launch_bounds__(256)
void gemm_f16(const float* __restrict__ A, const float* __restrict__ W,
              const float* __restrict__ bias, float* __restrict__ C,
              int M, int K, int N)
{
    __shared__ uint32_t As[128][20];   // row=m, 16 k-words (half2) + 4 pad
    __shared__ uint32_t Bs[32][36];    // row=k, 32 n-words (half2) + 4 pad

    int tid = threadIdx.x;
    int lane = tid & 31, w = tid >> 5;
    int g = lane >> 2, tg = lane & 3;
    int wm = (w & 3) * 32, wn = (w >> 2) * 32;
    int m0 = blockIdx.y * 128, n0 = blockIdx.x * 64;

    // ldmatrix lane geometry
    int la  = lane & 15;                      // A row offset
    int ha  = (lane >> 4) * 4;                // A word offset (k-high half)
    int lbk = (lane & 7) + ((lane >> 3) & 1) * 8;  // B k-row offset (trans)
    int hbn = (lane >> 4) * 4;                // B n-word offset (matrix pair)

    uint32_t asb = (uint32_t)__cvta_generic_to_shared(&As[0][0]);
    uint32_t bsb = (uint32_t)__cvta_generic_to_shared(&Bs[0][0]);

    float acc[2][4][4] = {};
    float4 areg[4], breg[2];

    auto ldt = [&](int k0) {
#pragma unroll
        for (int p = 0; p < 4; p++) {
            int idx = tid + p * 256;
            int r = idx >> 3, c4 = idx & 7;
            areg[p] = *(const float4*)(A + (size_t)(m0 + r) * K + k0 + c4 * 4);
        }
#pragma unroll
        for (int p = 0; p < 2; p++) {
            int idx = tid + p * 256;
            int kr = idx >> 4, c4 = idx & 15;
            breg[p] = *(const float4*)(W + (size_t)(k0 + kr) * N + n0 + c4 * 4);
        }
    };

    int niter = K / 32;
    ldt(0);

    for (int i = 0; i < niter; i++) {
        __syncthreads();   // previous tile consumed
#pragma unroll
        for (int p = 0; p < 4; p++) {
            int idx = tid + p * 256;
            int r = idx >> 3, c4 = idx & 7;
            uint2 u = make_uint2(packh2(areg[p].x, areg[p].y),
                                 packh2(areg[p].z, areg[p].w));
            *(uint2*)&As[r][c4*2] = u;
        }
#pragma unroll
        for (int p = 0; p < 2; p++) {
            int idx = tid + p * 256;
            int kr = idx >> 4, c4 = idx & 15;
            uint2 u = make_uint2(packh2(breg[p].x, breg[p].y),
                                 packh2(breg[p].z, breg[p].w));
            *(uint2*)&Bs[kr][c4*2] = u;
        }
        __syncthreads();

        if (i + 1 < niter) ldt((i + 1) * 32);   // overlap next tile's LDGs

#pragma unroll
        for (int ks = 0; ks < 2; ks++) {
            uint32_t af[2][4], bf[4][2];
#pragma unroll
            for (int mt = 0; mt < 2; mt++) {
                uint32_t addr = asb + ((wm + mt*16 + la) * 20 + ks*8 + ha) * 4;
                LDSM4(af[mt][0], af[mt][1], af[mt][2], af[mt][3], addr);
            }
            // B via ldmatrix.trans from k-major Bs: covers n16 per x4
#pragma unroll
            for (int ntp = 0; ntp < 2; ntp++) {
                uint32_t addr = bsb + ((ks*16 + lbk) * 36 + wn/2 + ntp*8 + hbn) * 4;
                LDSM4T(bf[2*ntp][0], bf[2*ntp][1], bf[2*ntp+1][0], bf[2*ntp+1][1], addr);
            }
#pragma unroll
            for (int mt = 0; mt < 2; mt++)
#pragma unroll
                for (int nt = 0; nt < 4; nt++)
                    mma_f16(acc[mt][nt], af[mt], bf[nt]);
        }
    }

    // epilogue: bias (+ optional interleaved RoPE), store (fp32)
#pragma unroll
    for (int mt = 0; mt < 2; mt++) {
        int r0 = m0 + wm + mt * 16 + g;
#pragma unroll
        for (int nt = 0; nt < 4; nt++) {
            int c = n0 + wn + nt * 8 + tg * 2;
            float2 bb = *(const float2*)(bias + c);
            float2 v0 = make_float2(acc[mt][nt][0] + bb.x, acc[mt][nt][1] + bb.y);
            float2 v1 = make_float2(acc[mt][nt][2] + bb.x, acc[mt][nt][3] + bb.y);
            if (DO_ROPE) {
                int pair = (c & (HD - 1)) >> 1;
                float inv = powf(10000.0f, -(float)(2 * pair) / (float)HD);
                float sn0, cs0, sn1, cs1;
                sincosf((float)(r0 & (Tsz - 1)) * inv, &sn0, &cs0);
                sincosf((float)((r0 + 8) & (Tsz - 1)) * inv, &sn1, &cs1);
                float e0 = v0.x, o0 = v0.y;
                v0.x = e0 * cs0 - o0 * sn0;  v0.y = e0 * sn0 + o0 * cs0;
                float e1 = v1.x, o1 = v1.y;
                v1.x = e1 * cs1 - o1 * sn1;  v1.y = e1 * sn1 + o1 * cs1;
            }
            *(float2*)(C + (size_t)r0 * N + c)       = v0;
            *(float2*)(C + (size_t)(r0 + 8) * N + c) = v1;
        }
    }
}

// ---------------------------------------------------------------------------
// Flash attention, fp16 tensor cores + ldmatrix (unchanged from R7 — proven).
// ---------------------------------------------------------------------------
__global__ __launch_bounds__(256)
void attn_f16(const float* __restrict__ q, const float* __restrict__ k,
              const float* __restrict__ v, float* __restrict__ o)
{
    extern __shared__ uint32_t smu[];
    uint32_t (*Qs)[36] = (uint32_t(*)[36])smu;                    // [128][36]
    uint32_t (*Ks)[36] = (uint32_t(*)[36])(smu + 128*36);         // [64][36]
    uint32_t (*Vt)[36] = (uint32_t(*)[36])(smu + (128+64)*36);    // [64][36]
    uint32_t (*Ps)[36] = (uint32_t(*)[36])(smu + (128+64+64)*36); // [128][36]
    float2*  red       = (float2*)(smu + (128+64+64+128)*36);     // [128][2]

    int b  = blockIdx.z;
    int h  = blockIdx.y;
    int qb = gridDim.x - 1 - blockIdx.x;   // heavy blocks first
    int q0 = qb * QB;
    int kvh = h >> 2;

    int tid = threadIdx.x;
    int lane = tid & 31, w = tid >> 5;
    int g = lane >> 2, tg = lane & 3;
    int wm = (w >> 1) * 32;
    int wn = w & 1;

    int la = lane & 15;
    int ha = (lane >> 4) * 4;
    int lb = (lane & 7) + (lane >> 4) * 8;
    int hb = ((lane >> 3) & 1) * 4;

    uint32_t qsb = (uint32_t)__cvta_generic_to_shared(&Qs[0][0]);
    uint32_t ksb = (uint32_t)__cvta_generic_to_shared(&Ks[0][0]);
    uint32_t vtb = (uint32_t)__cvta_generic_to_shared(&Vt[0][0]);
    uint32_t psb = (uint32_t)__cvta_generic_to_shared(&Ps[0][0]);

    {
        const float* qbase = q + (size_t)(b * Tsz + q0) * Csz + h * HD;
#pragma unroll
        for (int p = 0; p < 8; p++) {
            int i4 = tid + p * 256;
            int r = i4 >> 4, c4 = i4 & 15;
            float4 t = *(const float4*)(qbase + (size_t)r * Csz + c4 * 4);
            uint2 u = make_uint2(packh2(t.x * 0.125f, t.y * 0.125f),
                                 packh2(t.z * 0.125f, t.w * 0.125f));
            *(uint2*)&Qs[r][c4*2] = u;
        }
    }

    float mrun[2][2], lrun[2][2];
    float oacc[2][4][4] = {};
#pragma unroll
    for (int mt = 0; mt < 2; mt++)
#pragma unroll
        for (int ri = 0; ri < 2; ri++) { mrun[mt][ri] = -1e30f; lrun[mt][ri] = 0.f; }

    float4 kreg[4], vreg[4];
    auto ldkv = [&](int kb) {
        const float* kp = k + (size_t)(b * Tsz + kb * 64) * KVC + kvh * HD;
        const float* vp = v + (size_t)(b * Tsz + kb * 64) * KVC + kvh * HD;
#pragma unroll
        for (int p = 0; p < 4; p++) {
            int idx = tid + p * 256;
            int key = idx >> 4, c4 = idx & 15;
            kreg[p] = *(const float4*)(kp + (size_t)key * KVC + c4 * 4);
        }
#pragma unroll
        for (int p = 0; p < 2; p++) {
            int idx = tid + p * 256;
            int k2 = idx & 31, c4 = idx >> 5;
            vreg[p*2+0] = *(const float4*)(vp + (size_t)(2*k2  ) * KVC + c4 * 4);
            vreg[p*2+1] = *(const float4*)(vp + (size_t)(2*k2+1) * KVC + c4 * 4);
        }
    };

    int kb_max = 2 * qb + 1;
    ldkv(0);

    for (int kb = 0; kb <= kb_max; kb++) {
        __syncthreads();
#pragma unroll
        for (int p = 0; p < 4; p++) {
            int idx = tid + p * 256;
            int key = idx >> 4, c4 = idx & 15;
            uint2 u = make_uint2(packh2(kreg[p].x, kreg[p].y),
                                 packh2(kreg[p].z, kreg[p].w));
            *(uint2*)&Ks[key][c4*2] = u;
        }
#pragma unroll
        for (int p = 0; p < 2; p++) {
            int idx = tid + p * 256;
            int k2 = idx & 31, c4 = idx >> 5;
            float4 v0 = vreg[p*2+0], v1 = vreg[p*2+1];
            Vt[c4*4+0][k2] = packh2(v0.x, v1.x);
            Vt[c4*4+1][k2] = packh2(v0.y, v1.y);
            Vt[c4*4+2][k2] = packh2(v0.z, v1.z);
            Vt[c4*4+3][k2] = packh2(v0.w, v1.w);
        }
        __syncthreads();

        if (kb < kb_max) ldkv(kb + 1);

        float s[2][4][4] = {};
#pragma unroll
        for (int ks = 0; ks < 4; ks++) {
            uint32_t af[2][4], bf[4][2];
#pragma unroll
            for (int mt = 0; mt < 2; mt++) {
                uint32_t addr = qsb + ((wm + mt*16 + la) * 36 + ks*8 + ha) * 4;
                LDSM4(af[mt][0], af[mt][1], af[mt][2], af[mt][3], addr);
            }
#pragma unroll
            for (int ntp = 0; ntp < 2; ntp++) {
                uint32_t addr = ksb + ((wn*32 + ntp*16 + lb) * 36 + ks*8 + hb) * 4;
                LDSM4(bf[2*ntp][0], bf[2*ntp][1], bf[2*ntp+1][0], bf[2*ntp+1][1], addr);
            }
#pragma unroll
            for (int mt = 0; mt < 2; mt++)
#pragma unroll
                for (int nt = 0; nt < 4; nt++)
                    mma_f16(s[mt][nt], af[mt], bf[nt]);
        }

        if (kb >= 2 * qb) {
#pragma unroll
            for (int mt = 0; mt < 2; mt++) {
                int row0 = q0 + wm + mt * 16 + g;
#pragma unroll
                for (int nt = 0; nt < 4; nt++) {
                    int col = kb * 64 + wn * 32 + nt * 8 + 2 * tg;
                    if (col     > row0    ) s[mt][nt][0] = -1e30f;
                    if (col + 1 > row0    ) s[mt][nt][1] = -1e30f;
                    if (col     > row0 + 8) s[mt][nt][2] = -1e30f;
                    if (col + 1 > row0 + 8) s[mt][nt][3] = -1e30f;
                }
            }
        }

        float mh[2][2], sh[2][2];
#pragma unroll
        for (int mt = 0; mt < 2; mt++)
#pragma unroll
            for (int ri = 0; ri < 2; ri++) {
                float mx = -1e30f;
#pragma unroll
                for (int nt = 0; nt < 4; nt++) {
                    mx = fmaxf(mx, s[mt][nt][2*ri]);
                    mx = fmaxf(mx, s[mt][nt][2*ri+1]);
                }
                mx = fmaxf(mx, __shfl_xor_sync(0xffffffffu, mx, 1));
                mx = fmaxf(mx, __shfl_xor_sync(0xffffffffu, mx, 2));
                float sum = 0.f;
#pragma unroll
                for (int nt = 0; nt < 4; nt++) {
                    float p0 = __expf(s[mt][nt][2*ri]   - mx);
                    float p1 = __expf(s[mt][nt][2*ri+1] - mx);
                    s[mt][nt][2*ri] = p0; s[mt][nt][2*ri+1] = p1;
                    sum += p0 + p1;
                }
                sum += __shfl_xor_sync(0xffffffffu, sum, 1);
                sum += __shfl_xor_sync(0xffffffffu, sum, 2);
                mh[mt][ri] = mx; sh[mt][ri] = sum;
            }

        if (tg == 0) {
#pragma unroll
            for (int mt = 0; mt < 2; mt++)
#pragma unroll
                for (int ri = 0; ri < 2; ri++)
                    red[(wm + mt*16 + ri*8 + g) * 2 + wn] = make_float2(mh[mt][ri], sh[mt][ri]);
        }
        __syncthreads();

#pragma unroll
        for (int mt = 0; mt < 2; mt++)
#pragma unroll
            for (int ri = 0; ri < 2; ri++) {
                int rl = wm + mt*16 + ri*8 + g;
                float2 r0 = red[rl*2 + 0];
                float2 r1 = red[rl*2 + 1];
                float mold = mrun[mt][ri];
                float mnew = fmaxf(mold, fmaxf(r0.x, r1.x));
                float corr = __expf(mold - mnew);
                lrun[mt][ri] = lrun[mt][ri] * corr
                             + r0.y * __expf(r0.x - mnew)
                             + r1.y * __expf(r1.x - mnew);
                mrun[mt][ri] = mnew;
                float pscale = __expf(mh[mt][ri] - mnew);
#pragma unroll
                for (int nt = 0; nt < 4; nt++) {
                    oacc[mt][nt][2*ri]   *= corr;
                    oacc[mt][nt][2*ri+1] *= corr;
                    Ps[rl][wn*16 + nt*4 + tg] =
                        packh2(s[mt][nt][2*ri] * pscale, s[mt][nt][2*ri+1] * pscale);
                }
            }
        __syncthreads();

#pragma unroll
        for (int ks = 0; ks < 4; ks++) {
            uint32_t af[2][4], bf[4][2];
#pragma unroll
            for (int mt = 0; mt < 2; mt++) {
                uint32_t addr = psb + ((wm + mt*16 + la) * 36 + ks*8 + ha) * 4;
                LDSM4(af[mt][0], af[mt][1], af[mt][2], af[mt][3], addr);
            }
#pragma unroll
            for (int ntp = 0; ntp < 2; ntp++) {
                uint32_t addr = vtb + ((wn*32 + ntp*16 + lb) * 36 + ks*8 + hb) * 4;
                LDSM4(bf[2*ntp][0], bf[2*ntp][1], bf[2*ntp+1][0], bf[2*ntp+1][1], addr);
            }
#pragma unroll
            for (int mt = 0; mt < 2; mt++)
#pragma unroll
                for (int nt = 0; nt < 4; nt++)
                    mma_f16(oacc[mt][nt], af[mt], bf[nt]);
        }
    }

    float* obase = o + (size_t)(b * Tsz + q0) * Csz + h * HD;
#pragma unroll
    for (int mt = 0; mt < 2; mt++)
#pragma unroll
        for (int ri = 0; ri < 2; ri++) {
            int rl = wm + mt*16 + ri*8 + g;
            float inv = 1.0f / lrun[mt][ri];
#pragma unroll
            for (int nt = 0; nt < 4; nt++) {
                float2 r2 = make_float2(oacc[mt][nt][2*ri] * inv, oacc[mt][nt][2*ri+1] * inv);
                *(float2*)(obase + (size_t)rl * Csz + wn*32 + nt*8 + 2*tg) = r2;
            }
        }
}

// ---------------------------------------------------------------------------
extern "C" void kernel_launch(void* const* d_in, const int* in_sizes, int n_in,
                              void* d_out, int out_size)
{
    const float* x   = (const float*)d_in[0];
    const float* w_q = (const float*)d_in[1];
    const float* b_q = (const float*)d_in[2];
    const float* w_k = (const float*)d_in[3];
    const float* b_k = (const float*)d_in[4];
    const float* w_v = (const float*)d_in[5];
    const float* b_v = (const float*)d_in[6];
    const float* w_o = (const float*)d_in[7];
    const float* b_o = (const float*)d_in[8];
    float* out = (float*)d_out;

    float *q, *k, *v, *ao;
    cudaGetSymbolAddress((void**)&q,  g_q);
    cudaGetSymbolAddress((void**)&k,  g_k);
    cudaGetSymbolAddress((void**)&v,  g_v);
    cudaGetSymbolAddress((void**)&ao, g_ao);

    // projections (fp16 tensor cores; RoPE fused into Q and K epilogues)
    gemm_f16<true ><<<dim3(Csz/64, Mrows/128), 256>>>(x, w_q, b_q, q, Mrows, Csz, Csz);
    gemm_f16<true ><<<dim3(KVC/64, Mrows/128), 256>>>(x, w_k, b_k, k, Mrows, Csz, KVC);
    gemm_f16<false><<<dim3(KVC/64, Mrows/128), 256>>>(x, w_v, b_v, v, Mrows, Csz, KVC);

    // flash attention (fp16 + ldmatrix, 128 q-rows per CTA)
    {
        int smem = (128+64+64+128) * 36 * 4 + 128 * 2 * 8;   // 57344
        cudaFuncSetAttribute(attn_f16, cudaFuncAttributeMaxDynamicSharedMemorySize, smem);
        attn_f16<<<dim3(Tsz/QB, NH, Bsz), 256, smem>>>(q, k, v, ao);
    }

    // output projection
    gemm_f16<false><<<dim3(Csz/64, Mrows/128), 256>>>(ao, w_o, b_o, out, Mrows, Csz, Csz);
}